// round 3
// baseline (speedup 1.0000x reference)
#include <cuda_runtime.h>
#include <cuda_bf16.h>

// Problem constants (fixed shapes from reference setup_inputs)
#define BT    16384      // B*T = 16*1024
#define HID   512
#define NP    30         // 3*K gaussian params per (b,t)
#define NU    600
#define NA    80
#define NK    10

// Scratch: transposed exp'ed params [p][bt].
// p in [0,10): a_k ; [10,20): -b_k ; [20,30): kappa_k
__device__ float g_par[NP * BT];

// ---------------------------------------------------------------------------
// Kernel 1: params = lstm_out @ W + bias, then exp, store transposed.
// Grid: 128 blocks x 128 t-rows each. Block 128 threads.
// Thread owns 4 t-rows x 8 p-cols. tg = tid>>2, pg = tid&3.
// ---------------------------------------------------------------------------
__global__ __launch_bounds__(128) void k1_gemm_exp(
    const float* __restrict__ lstm,
    const float* __restrict__ W,
    const float* __restrict__ bias)
{
    __shared__ float sA[128 * 33];   // [t][h] chunk, stride 33 (conflict-free)
    __shared__ float sW[32 * 32];    // [h][p] chunk, p padded 30->32 (zeros)

    const int tid = threadIdx.x;
    const int t0  = blockIdx.x * 128;
    const int pg  = tid & 3;    // p group: p in [pg*8, pg*8+8)
    const int tg  = tid >> 2;   // t group: t in [tg*4, tg*4+4)

    float acc[4][8];
    #pragma unroll
    for (int i = 0; i < 4; i++)
        #pragma unroll
        for (int j = 0; j < 8; j++) acc[i][j] = 0.f;

    // zero the p=30,31 pad once (covered by first __syncthreads below)
    if (tid < 64) sW[(tid >> 1) * 32 + 30 + (tid & 1)] = 0.f;

    for (int hc = 0; hc < HID; hc += 32) {
        __syncthreads();
        // Load A tile: 128 rows x 32 h-floats, coalesced float4 (8 threads/row)
        #pragma unroll
        for (int j = 0; j < 8; j++) {
            int idx = tid + 128 * j;          // float4 index 0..1023
            int row = idx >> 3;
            int c   = idx & 7;
            float4 v = *reinterpret_cast<const float4*>(
                lstm + (size_t)(t0 + row) * HID + hc + c * 4);
            float* d = &sA[row * 33 + c * 4];
            d[0] = v.x; d[1] = v.y; d[2] = v.z; d[3] = v.w;
        }
        // Load W tile: 32 h x 30 p (row-major contiguous in global)
        for (int idx = tid; idx < 32 * NP; idx += 128) {
            int h = idx / NP;
            int p = idx - h * NP;
            sW[h * 32 + p] = W[hc * NP + idx];
        }
        __syncthreads();

        #pragma unroll 8
        for (int h = 0; h < 32; h++) {
            float av[4];
            #pragma unroll
            for (int i = 0; i < 4; i++) av[i] = sA[(tg * 4 + i) * 33 + h];
            float wv[8];
            #pragma unroll
            for (int j = 0; j < 8; j++) wv[j] = sW[h * 32 + pg * 8 + j];
            #pragma unroll
            for (int i = 0; i < 4; i++)
                #pragma unroll
                for (int j = 0; j < 8; j++)
                    acc[i][j] = fmaf(av[i], wv[j], acc[i][j]);
        }
    }

    // Epilogue: +bias, exp, negate b-block, store transposed [p][bt]
    #pragma unroll
    for (int i = 0; i < 4; i++) {
        int t = t0 + tg * 4 + i;
        #pragma unroll
        for (int j = 0; j < 8; j++) {
            int p = pg * 8 + j;
            if (p < NP) {
                float e = expf(acc[i][j] + bias[p]);
                if (p >= NK && p < 2 * NK) e = -e;   // store -b
                g_par[p * BT + t] = e;
            }
        }
    }
}

// ---------------------------------------------------------------------------
// Kernel 2: phi[b,t,u] = sum_k a*exp(-b*(kappa-u)^2) (truncated at analytic
// cutoff), fused with out[b,t,a] = sum_u phi * char_seq[b,u,a].
// One thread per (b,t), 80 fp32 accumulators for the a-outputs.
// char_seq row addresses are warp-uniform -> broadcast loads, L1-resident.
// ---------------------------------------------------------------------------
__global__ __launch_bounds__(128) void k2_window(
    const float* __restrict__ charseq,
    float* __restrict__ out)
{
    const int bt = blockIdx.x * 128 + threadIdx.x;
    const int b  = bt >> 10;   // T = 1024

    float a[NK], nb[NK], kk[NK];
    #pragma unroll
    for (int k = 0; k < NK; k++) {
        a[k]  = g_par[k * BT + bt];
        nb[k] = g_par[(NK + k) * BT + bt];      // -b_k (negative)
        kk[k] = g_par[(2 * NK + k) * BT + bt];
    }

    // u beyond kappa + sqrt(48/b) contributes < exp(-48) ~ 1.4e-21 per term:
    // truncation error <= ~1e-16 absolute vs outputs of O(1).
    float cut = 1.f;
    #pragma unroll
    for (int k = 0; k < NK; k++)
        cut = fmaxf(cut, kk[k] + __fsqrt_rn(__fdividef(48.f, -nb[k])));
    int ucut = min(NU, (int)cut + 1);

    float acc[NA];
    #pragma unroll
    for (int j = 0; j < NA; j++) acc[j] = 0.f;

    const float4* crow = reinterpret_cast<const float4*>(
        charseq + (size_t)b * NU * NA);

    for (int u = 0; u < ucut; u++) {
        const float uf = (float)u;
        float phi = 0.f;
        #pragma unroll
        for (int k = 0; k < NK; k++) {
            float d = kk[k] - uf;
            phi += a[k] * __expf(nb[k] * d * d);
        }
        const float4* r = crow + u * (NA / 4);
        #pragma unroll
        for (int j = 0; j < NA / 4; j++) {
            float4 c = r[j];
            acc[4 * j + 0] = fmaf(phi, c.x, acc[4 * j + 0]);
            acc[4 * j + 1] = fmaf(phi, c.y, acc[4 * j + 1]);
            acc[4 * j + 2] = fmaf(phi, c.z, acc[4 * j + 2]);
            acc[4 * j + 3] = fmaf(phi, c.w, acc[4 * j + 3]);
        }
    }

    float4* op = reinterpret_cast<float4*>(out + (size_t)bt * NA);
    #pragma unroll
    for (int j = 0; j < NA / 4; j++)
        op[j] = make_float4(acc[4 * j], acc[4 * j + 1],
                            acc[4 * j + 2], acc[4 * j + 3]);
}

// ---------------------------------------------------------------------------
extern "C" void kernel_launch(void* const* d_in, const int* in_sizes, int n_in,
                              void* d_out, int out_size)
{
    const float* lstm = (const float*)d_in[0];   // [16,1024,512]
    const float* cs   = (const float*)d_in[1];   // [16,600,80]
    const float* W    = (const float*)d_in[2];   // [512,30]
    const float* bias = (const float*)d_in[3];   // [30]
    float* out = (float*)d_out;                  // [16,1024,80]

    (void)in_sizes; (void)n_in; (void)out_size;

    k1_gemm_exp<<<BT / 128, 128>>>(lstm, W, bias);
    k2_window<<<BT / 128, 128>>>(cs, out);
}

// round 4
// speedup vs baseline: 1.5247x; 1.5247x over previous
#include <cuda_runtime.h>
#include <cuda_bf16.h>

// Problem constants (fixed shapes from reference setup_inputs)
#define BT    16384      // B*T = 16*1024
#define HID   512
#define NP    30         // 3*K gaussian params per (b,t)
#define NU    600
#define NA    80
#define NK    10

// Scratch: transposed exp'ed params [p][bt].
// p in [0,10): a_k ; [10,20): -b_k ; [20,30): kappa_k
__device__ float g_par[NP * BT];

// ---------------------------------------------------------------------------
// Kernel 1: params = lstm_out @ W + bias, then exp, store transposed.
// Grid: 256 blocks x 64 t-rows each. Block 128 threads.
// Thread owns 2 t-rows x 8 p-cols. tg = tid>>2 (32 groups), pg = tid&3.
// ---------------------------------------------------------------------------
__global__ __launch_bounds__(128) void k1_gemm_exp(
    const float* __restrict__ lstm,
    const float* __restrict__ W,
    const float* __restrict__ bias)
{
    __shared__ float sA[64 * 33];    // [t][h] chunk, stride 33 (conflict-free)
    __shared__ float sW[32 * 32];    // [h][p] chunk, p padded 30->32 (zeros)

    const int tid = threadIdx.x;
    const int t0  = blockIdx.x * 64;
    const int pg  = tid & 3;    // p group: p in [pg*8, pg*8+8)
    const int tg  = tid >> 2;   // t group: t in [tg*2, tg*2+2)

    float acc[2][8];
    #pragma unroll
    for (int i = 0; i < 2; i++)
        #pragma unroll
        for (int j = 0; j < 8; j++) acc[i][j] = 0.f;

    // zero the p=30,31 pad once (covered by first __syncthreads below)
    if (tid < 64) sW[(tid >> 1) * 32 + 30 + (tid & 1)] = 0.f;

    for (int hc = 0; hc < HID; hc += 32) {
        __syncthreads();
        // Load A tile: 64 rows x 32 h-floats, coalesced float4 (8 threads/row)
        #pragma unroll
        for (int j = 0; j < 4; j++) {
            int idx = tid + 128 * j;          // float4 index 0..511
            int row = idx >> 3;
            int c   = idx & 7;
            float4 v = *reinterpret_cast<const float4*>(
                lstm + (size_t)(t0 + row) * HID + hc + c * 4);
            float* d = &sA[row * 33 + c * 4];
            d[0] = v.x; d[1] = v.y; d[2] = v.z; d[3] = v.w;
        }
        // Load W tile: 32 h x 30 p (row-major contiguous in global)
        for (int idx = tid; idx < 32 * NP; idx += 128) {
            int h = idx / NP;
            int p = idx - h * NP;
            sW[h * 32 + p] = W[hc * NP + idx];
        }
        __syncthreads();

        #pragma unroll 8
        for (int h = 0; h < 32; h++) {
            float av[2];
            #pragma unroll
            for (int i = 0; i < 2; i++) av[i] = sA[(tg * 2 + i) * 33 + h];
            float wv[8];
            #pragma unroll
            for (int j = 0; j < 8; j++) wv[j] = sW[h * 32 + pg * 8 + j];
            #pragma unroll
            for (int i = 0; i < 2; i++)
                #pragma unroll
                for (int j = 0; j < 8; j++)
                    acc[i][j] = fmaf(av[i], wv[j], acc[i][j]);
        }
    }

    // Epilogue: +bias, exp, negate b-block, store transposed [p][bt]
    #pragma unroll
    for (int i = 0; i < 2; i++) {
        int t = t0 + tg * 2 + i;
        #pragma unroll
        for (int j = 0; j < 8; j++) {
            int p = pg * 8 + j;
            if (p < NP) {
                float e = expf(acc[i][j] + bias[p]);
                if (p >= NK && p < 2 * NK) e = -e;   // store -b
                g_par[p * BT + t] = e;
            }
        }
    }
}

// ---------------------------------------------------------------------------
// Kernel 2: phi[b,t,u] = sum_k a*exp(-b*(kappa-u)^2) (truncated at analytic
// cutoff), fused with out[b,t,a] = sum_u phi * char_seq[b,u,a].
// FOUR threads per (b,t): sub = gt&3 owns a-columns [sub*20, sub*20+20).
// Each sub-thread recomputes phi (cheap: MUFU far from saturation); registers
// drop to ~65 -> 4x threads, ~6x resident warps vs v1.
// ---------------------------------------------------------------------------
#define SUBS 4
#define APT  (NA / SUBS)   // 20 floats = 5 float4 per sub-thread

__global__ __launch_bounds__(256) void k2_window(
    const float* __restrict__ charseq,
    float* __restrict__ out)
{
    const int gt  = blockIdx.x * 256 + threadIdx.x;
    const int bt  = gt >> 2;
    const int sub = gt & 3;
    const int b   = bt >> 10;   // T = 1024

    float a[NK], nb[NK], kk[NK];
    #pragma unroll
    for (int k = 0; k < NK; k++) {
        a[k]  = g_par[k * BT + bt];
        nb[k] = g_par[(NK + k) * BT + bt];      // -b_k (negative)
        kk[k] = g_par[(2 * NK + k) * BT + bt];
    }

    // u beyond kappa + sqrt(48/b) contributes < exp(-48) ~ 1.4e-21 per term:
    // truncation error <= ~1e-16 absolute vs outputs of O(1).
    float cut = 1.f;
    #pragma unroll
    for (int k = 0; k < NK; k++)
        cut = fmaxf(cut, kk[k] + __fsqrt_rn(__fdividef(48.f, -nb[k])));
    const int ucut = min(NU, (int)cut + 1);

    float acc[APT];
    #pragma unroll
    for (int j = 0; j < APT; j++) acc[j] = 0.f;

    const float* crow = charseq + (size_t)b * NU * NA + sub * APT;

    for (int u = 0; u < ucut; u++) {
        const float uf = (float)u;
        float phi = 0.f;
        #pragma unroll
        for (int k = 0; k < NK; k++) {
            float d = kk[k] - uf;
            phi += a[k] * __expf(nb[k] * d * d);
        }
        const float4* r = reinterpret_cast<const float4*>(crow + u * NA);
        #pragma unroll
        for (int j = 0; j < APT / 4; j++) {
            float4 c = r[j];
            acc[4 * j + 0] = fmaf(phi, c.x, acc[4 * j + 0]);
            acc[4 * j + 1] = fmaf(phi, c.y, acc[4 * j + 1]);
            acc[4 * j + 2] = fmaf(phi, c.z, acc[4 * j + 2]);
            acc[4 * j + 3] = fmaf(phi, c.w, acc[4 * j + 3]);
        }
    }

    float4* op = reinterpret_cast<float4*>(out + (size_t)bt * NA + sub * APT);
    #pragma unroll
    for (int j = 0; j < APT / 4; j++)
        op[j] = make_float4(acc[4 * j], acc[4 * j + 1],
                            acc[4 * j + 2], acc[4 * j + 3]);
}

// ---------------------------------------------------------------------------
extern "C" void kernel_launch(void* const* d_in, const int* in_sizes, int n_in,
                              void* d_out, int out_size)
{
    const float* lstm = (const float*)d_in[0];   // [16,1024,512]
    const float* cs   = (const float*)d_in[1];   // [16,600,80]
    const float* W    = (const float*)d_in[2];   // [512,30]
    const float* bias = (const float*)d_in[3];   // [30]
    float* out = (float*)d_out;                  // [16,1024,80]

    (void)in_sizes; (void)n_in; (void)out_size;

    k1_gemm_exp<<<BT / 64, 128>>>(lstm, W, bias);
    k2_window<<<(BT * SUBS) / 256, 256>>>(cs, out);
}

// round 5
// speedup vs baseline: 1.5802x; 1.0364x over previous
#include <cuda_runtime.h>
#include <cuda_bf16.h>

// Problem constants (fixed shapes from reference setup_inputs)
#define BT    16384      // B*T = 16*1024
#define HID   512
#define NP    30         // 3*K gaussian params per (b,t)
#define NU    600
#define NA    80
#define NK    10

// Scratch: transposed exp'ed params [p][bt].
// p in [0,10): a_k ; [10,20): -b_k ; [20,30): kappa_k
__device__ float g_par[NP * BT];

// ---------------------------------------------------------------------------
// Kernel 1: params = lstm_out @ W + bias, then exp, store transposed.
// Grid: 128 blocks x 128 t-rows. Block 256 threads; thread owns 4t x 4p.
// tg = tid>>3 (32 groups of 4 rows), pg = tid&7 (8 groups of 4 p-cols).
// 8 warps/CTA -> ~1.7 warps/SMSP to hide LDS latency.
// ---------------------------------------------------------------------------
__global__ __launch_bounds__(256) void k1_gemm_exp(
    const float* __restrict__ lstm,
    const float* __restrict__ W,
    const float* __restrict__ bias)
{
    __shared__ float sA[128 * 33];   // [t][h] chunk, stride 33 (conflict-free)
    __shared__ float sW[32 * 32];    // [h][p] chunk, p padded 30->32 (zeros)

    const int tid = threadIdx.x;
    const int t0  = blockIdx.x * 128;
    const int pg  = tid & 7;    // p in [pg*4, pg*4+4)
    const int tg  = tid >> 3;   // t in [tg*4, tg*4+4)

    float acc[4][4];
    #pragma unroll
    for (int i = 0; i < 4; i++)
        #pragma unroll
        for (int j = 0; j < 4; j++) acc[i][j] = 0.f;

    // zero the p=30,31 pad once (covered by first __syncthreads below)
    if (tid < 64) sW[(tid >> 1) * 32 + 30 + (tid & 1)] = 0.f;

    for (int hc = 0; hc < HID; hc += 32) {
        __syncthreads();
        // Load A tile: 128 rows x 32 h-floats, coalesced float4 (8 thr/row)
        #pragma unroll
        for (int j = 0; j < 4; j++) {
            int idx = tid + 256 * j;          // float4 index 0..1023
            int row = idx >> 3;
            int c   = idx & 7;
            float4 v = *reinterpret_cast<const float4*>(
                lstm + (size_t)(t0 + row) * HID + hc + c * 4);
            float* d = &sA[row * 33 + c * 4];
            d[0] = v.x; d[1] = v.y; d[2] = v.z; d[3] = v.w;
        }
        // Load W tile: 32 h x 30 p (row-major contiguous in global)
        for (int idx = tid; idx < 32 * NP; idx += 256) {
            int h = idx / NP;
            int p = idx - h * NP;
            sW[h * 32 + p] = W[hc * NP + idx];
        }
        __syncthreads();

        #pragma unroll 8
        for (int h = 0; h < 32; h++) {
            float av[4];
            #pragma unroll
            for (int i = 0; i < 4; i++) av[i] = sA[(tg * 4 + i) * 33 + h];
            float wv[4];
            #pragma unroll
            for (int j = 0; j < 4; j++) wv[j] = sW[h * 32 + pg * 4 + j];
            #pragma unroll
            for (int i = 0; i < 4; i++)
                #pragma unroll
                for (int j = 0; j < 4; j++)
                    acc[i][j] = fmaf(av[i], wv[j], acc[i][j]);
        }
    }

    // Epilogue: +bias, exp, negate b-block, store transposed [p][bt]
    #pragma unroll
    for (int i = 0; i < 4; i++) {
        int t = t0 + tg * 4 + i;
        #pragma unroll
        for (int j = 0; j < 4; j++) {
            int p = pg * 4 + j;
            if (p < NP) {
                float e = expf(acc[i][j] + bias[p]);
                if (p >= NK && p < 2 * NK) e = -e;   // store -b
                g_par[p * BT + t] = e;
            }
        }
    }
}

// ---------------------------------------------------------------------------
// Kernel 2: block of 128 threads owns 16 consecutive bt (same b: 16 | 1024).
// Phase 1: phi[bt][u] computed ONCE into smem (64-u chunks, analytic cutoff).
// Phase 2: 8 threads per bt, each owns 10 a-cols, consumes smem phi.
// Grid 1024 CTAs -> balanced across 148 SMs; no MUFU duplication.
// ---------------------------------------------------------------------------
#define BPB    16        // bt's per block
#define UCHUNK 64
#define SUBS   8
#define APT    (NA / SUBS)   // 10 a-cols per sub-thread

__global__ __launch_bounds__(128) void k2_window(
    const float* __restrict__ charseq,
    float* __restrict__ out)
{
    __shared__ float spar[NP * BPB];          // [p][bt_local]
    __shared__ float sphi[BPB][UCHUNK + 1];   // +1 pad: conflict-free column reads
    __shared__ int   sucut[BPB];
    __shared__ int   smaxcut;

    const int tid = threadIdx.x;
    const int bt0 = blockIdx.x * BPB;
    const int b   = bt0 >> 10;                // whole block shares b (16 | 1024)

    // Stage params for the 16 bt's: g_par is [p][bt] -> 16-wide coalesced runs
    #pragma unroll
    for (int j = 0; j < (NP * BPB + 127) / 128; j++) {
        int idx = tid + 128 * j;              // 0..479
        if (idx < NP * BPB) {
            int p  = idx >> 4;
            int bl = idx & 15;
            spar[p * BPB + bl] = g_par[p * BT + bt0 + bl];
        }
    }
    __syncthreads();

    // Per-bt analytic cutoff: u > kappa + sqrt(48/b) contributes < exp(-48).
    if (tid < BPB) {
        float cut = 1.f;
        #pragma unroll
        for (int k = 0; k < NK; k++) {
            float kkv = spar[(2 * NK + k) * BPB + tid];
            float nbv = spar[(NK + k) * BPB + tid];   // negative
            cut = fmaxf(cut, kkv + __fsqrt_rn(__fdividef(48.f, -nbv)));
        }
        sucut[tid] = min(NU, (int)cut + 1);
    }
    __syncthreads();
    if (tid == 0) {
        int m = 1;
        #pragma unroll
        for (int i = 0; i < BPB; i++) m = max(m, sucut[i]);
        smaxcut = m;
    }

    const int bl  = tid >> 3;                 // bt_local 0..15
    const int sub = tid & 7;                  // a-col group 0..7

    float a[NK], nb[NK], kk[NK];              // phase-1 params for this thread's bl
    #pragma unroll
    for (int k = 0; k < NK; k++) {
        a[k]  = spar[k * BPB + bl];
        nb[k] = spar[(NK + k) * BPB + bl];
        kk[k] = spar[(2 * NK + k) * BPB + bl];
    }

    float acc[APT];
    #pragma unroll
    for (int j = 0; j < APT; j++) acc[j] = 0.f;

    const float* crow = charseq + (size_t)b * NU * NA + sub * APT;

    __syncthreads();                          // smaxcut + sucut visible
    const int maxcut = smaxcut;
    const int ucut   = sucut[bl];

    for (int u0 = 0; u0 < maxcut; u0 += UCHUNK) {
        // Phase 1: thread (bl, sub) computes phi for u = u0+sub, +8, ... (+56)
        #pragma unroll
        for (int r = 0; r < UCHUNK / 8; r++) {
            int uo = sub + 8 * r;
            int u  = u0 + uo;
            if (u < ucut) {
                float uf  = (float)u;
                float phi = 0.f;
                #pragma unroll
                for (int k = 0; k < NK; k++) {
                    float d = kk[k] - uf;
                    phi += a[k] * __expf(nb[k] * d * d);
                }
                sphi[bl][uo] = phi;
            }
        }
        __syncthreads();

        // Phase 2: consume phi; thread owns a-cols [sub*10, sub*10+10)
        int uend = min(ucut, u0 + UCHUNK);
        for (int u = u0; u < uend; u++) {
            float phi = sphi[bl][u - u0];
            const float2* r2 = reinterpret_cast<const float2*>(crow + u * NA);
            #pragma unroll
            for (int j = 0; j < APT / 2; j++) {
                float2 c = r2[j];
                acc[2 * j + 0] = fmaf(phi, c.x, acc[2 * j + 0]);
                acc[2 * j + 1] = fmaf(phi, c.y, acc[2 * j + 1]);
            }
        }
        __syncthreads();
    }

    float2* op = reinterpret_cast<float2*>(out + (size_t)(bt0 + bl) * NA + sub * APT);
    #pragma unroll
    for (int j = 0; j < APT / 2; j++)
        op[j] = make_float2(acc[2 * j], acc[2 * j + 1]);
}

// ---------------------------------------------------------------------------
extern "C" void kernel_launch(void* const* d_in, const int* in_sizes, int n_in,
                              void* d_out, int out_size)
{
    const float* lstm = (const float*)d_in[0];   // [16,1024,512]
    const float* cs   = (const float*)d_in[1];   // [16,600,80]
    const float* W    = (const float*)d_in[2];   // [512,30]
    const float* bias = (const float*)d_in[3];   // [30]
    float* out = (float*)d_out;                  // [16,1024,80]

    (void)in_sizes; (void)n_in; (void)out_size;

    k1_gemm_exp<<<BT / 128, 256>>>(lstm, W, bias);
    k2_window<<<BT / BPB, 128>>>(cs, out);
}

// round 6
// speedup vs baseline: 2.0444x; 1.2937x over previous
#include <cuda_runtime.h>
#include <cuda_bf16.h>

// Problem constants (fixed shapes from reference setup_inputs)
#define BT    16384      // B*T = 16*1024
#define HID   512
#define NP    30         // 3*K gaussian params per (b,t)
#define NU    600
#define NA    80
#define NK    10

// Scratch: transposed exp'ed params [p][bt].
// p in [0,10): a_k ; [10,20): -b_k ; [20,30): kappa_k
__device__ float g_par[NP * BT];

// ---------------------------------------------------------------------------
// Kernel 1: params = lstm_out @ W + bias, then exp, store transposed.
// Grid 128 blocks x 128 t-rows; 256 threads; thread owns 4t x 4p.
// A tile stored TRANSPOSED sA[h][t ^ swz(h)] so both the per-h A read (4
// consecutive t) and the W read are single LDS.128: 2 LDS + 16 FFMA per h.
// Swizzle col = t ^ (4*(h>>2)) makes strided STS writes AND reads
// bank-conflict-free (verified lane-by-lane).
// ---------------------------------------------------------------------------
__global__ __launch_bounds__(256) void k1_gemm_exp(
    const float* __restrict__ lstm,
    const float* __restrict__ W,
    const float* __restrict__ bias)
{
    __shared__ float sA[32][132];    // [h][t-swizzled], stride 132 (16B-aligned cols)
    __shared__ float sW[32][32];     // [h][p], p padded 30->32 (zeros)

    const int tid = threadIdx.x;
    const int t0  = blockIdx.x * 128;
    const int pg  = tid & 7;    // p in [pg*4, pg*4+4)
    const int tg  = tid >> 3;   // t in [tg*4, tg*4+4)

    float acc[4][4];
    #pragma unroll
    for (int i = 0; i < 4; i++)
        #pragma unroll
        for (int j = 0; j < 4; j++) acc[i][j] = 0.f;

    // zero the p=30,31 pad once (covered by first __syncthreads below)
    if (tid < 64) sW[tid >> 1][30 + (tid & 1)] = 0.f;

    for (int hc = 0; hc < HID; hc += 32) {
        __syncthreads();
        // Load A tile transposed: 128 t-rows x 32 h. Thread reads float4 of
        // 4 consecutive h for one t, scatters to 4 rows of sA.
        #pragma unroll
        for (int j = 0; j < 4; j++) {
            int idx = tid + 256 * j;          // 0..1023
            int row = idx >> 3;               // t-local 0..127
            int c   = idx & 7;                // h-group (4 h each)
            float4 v = *reinterpret_cast<const float4*>(
                lstm + (size_t)(t0 + row) * HID + hc + c * 4);
            int col = row ^ (c * 4);          // swizzled t-column
            sA[4 * c + 0][col] = v.x;
            sA[4 * c + 1][col] = v.y;
            sA[4 * c + 2][col] = v.z;
            sA[4 * c + 3][col] = v.w;
        }
        // Load W tile: 32 h x 30 p (row-major contiguous in global)
        #pragma unroll
        for (int r = 0; r < 4; r++) {
            int idx = tid + 256 * r;          // 0..959 (<1024)
            if (idx < 32 * NP) {
                int h = idx / NP;
                int p = idx - h * NP;
                sW[h][p] = W[hc * NP + idx];
            }
        }
        __syncthreads();

        #pragma unroll
        for (int h = 0; h < 32; h++) {
            float4 av = *reinterpret_cast<const float4*>(
                &sA[h][4 * (tg ^ (h >> 2))]);
            float4 wv = *reinterpret_cast<const float4*>(&sW[h][4 * pg]);
            acc[0][0] = fmaf(av.x, wv.x, acc[0][0]);
            acc[0][1] = fmaf(av.x, wv.y, acc[0][1]);
            acc[0][2] = fmaf(av.x, wv.z, acc[0][2]);
            acc[0][3] = fmaf(av.x, wv.w, acc[0][3]);
            acc[1][0] = fmaf(av.y, wv.x, acc[1][0]);
            acc[1][1] = fmaf(av.y, wv.y, acc[1][1]);
            acc[1][2] = fmaf(av.y, wv.z, acc[1][2]);
            acc[1][3] = fmaf(av.y, wv.w, acc[1][3]);
            acc[2][0] = fmaf(av.z, wv.x, acc[2][0]);
            acc[2][1] = fmaf(av.z, wv.y, acc[2][1]);
            acc[2][2] = fmaf(av.z, wv.z, acc[2][2]);
            acc[2][3] = fmaf(av.z, wv.w, acc[2][3]);
            acc[3][0] = fmaf(av.w, wv.x, acc[3][0]);
            acc[3][1] = fmaf(av.w, wv.y, acc[3][1]);
            acc[3][2] = fmaf(av.w, wv.z, acc[3][2]);
            acc[3][3] = fmaf(av.w, wv.w, acc[3][3]);
        }
    }

    // Epilogue: +bias, exp, negate b-block, store transposed [p][bt]
    #pragma unroll
    for (int i = 0; i < 4; i++) {
        int t = t0 + tg * 4 + i;
        #pragma unroll
        for (int j = 0; j < 4; j++) {
            int p = pg * 4 + j;
            if (p < NP) {
                float e = expf(acc[i][j] + bias[p]);
                if (p >= NK && p < 2 * NK) e = -e;   // store -b
                g_par[p * BT + t] = e;
            }
        }
    }
}

// ---------------------------------------------------------------------------
// Kernel 2: block of 256 threads owns 32 consecutive bt (same b: 32 | 1024).
// Window is analytically bounded (b>=~0.1, kappa<=~7 -> ucut <= ~35 << 64),
// so the needed charseq rows fit one 20KB smem chunk: stage once, then the
// inner loop is pure LDS + FFMA (no LDG). phi computed once per (bt,u).
// ---------------------------------------------------------------------------
#define BPB    32        // bt's per block
#define UCHUNK 64
#define SUBS   8
#define APT    (NA / SUBS)   // 10 a-cols per sub-thread

__global__ __launch_bounds__(256) void k2_window(
    const float* __restrict__ charseq,
    float* __restrict__ out)
{
    __shared__ float spar[NP * BPB];          // [p][bt_local]  3.75 KB
    __shared__ float sphi[BPB][UCHUNK + 1];   // 8.1 KB, pad: conflict-free
    __shared__ float scs[UCHUNK][NA];         // 20 KB charseq chunk
    __shared__ int   sucut[BPB];
    __shared__ int   smaxcut;

    const int tid = threadIdx.x;
    const int bt0 = blockIdx.x * BPB;
    const int b   = bt0 >> 10;                // whole block shares b (32 | 1024)

    // Stage params: g_par is [p][bt] -> 32-wide coalesced runs
    #pragma unroll
    for (int j = 0; j < (NP * BPB + 255) / 256; j++) {
        int idx = tid + 256 * j;              // 0..959
        if (idx < NP * BPB) {
            int p  = idx >> 5;
            int bl = idx & 31;
            spar[p * BPB + bl] = g_par[p * BT + bt0 + bl];
        }
    }
    __syncthreads();

    // Per-bt analytic cutoff: u > kappa + sqrt(48/b) contributes < exp(-48).
    if (tid < BPB) {
        float cut = 1.f;
        #pragma unroll
        for (int k = 0; k < NK; k++) {
            float kkv = spar[(2 * NK + k) * BPB + tid];
            float nbv = spar[(NK + k) * BPB + tid];   // negative
            cut = fmaxf(cut, kkv + __fsqrt_rn(__fdividef(48.f, -nbv)));
        }
        sucut[tid] = min(NU, (int)cut + 1);
    }
    __syncthreads();
    if (tid == 0) {
        int m = 1;
        #pragma unroll
        for (int i = 0; i < BPB; i++) m = max(m, sucut[i]);
        smaxcut = m;
    }

    const int bl  = tid >> 3;                 // bt_local 0..31
    const int sub = tid & 7;                  // a-col group 0..7

    float a[NK], nb[NK], kk[NK];
    #pragma unroll
    for (int k = 0; k < NK; k++) {
        a[k]  = spar[k * BPB + bl];
        nb[k] = spar[(NK + k) * BPB + bl];
        kk[k] = spar[(2 * NK + k) * BPB + bl];
    }

    float acc[APT];
    #pragma unroll
    for (int j = 0; j < APT; j++) acc[j] = 0.f;

    const float* cbase = charseq + (size_t)b * NU * NA;

    __syncthreads();                          // smaxcut + sucut visible
    const int maxcut = smaxcut;
    const int ucut   = sucut[bl];

    for (int u0 = 0; u0 < maxcut; u0 += UCHUNK) {
        const int rows = min(UCHUNK, maxcut - u0);

        // Stage charseq rows [u0, u0+rows) : rows*20 float4s, coalesced
        for (int i = tid; i < rows * (NA / 4); i += 256) {
            int u = i / (NA / 4);
            int c = i - u * (NA / 4);
            float4 v = *reinterpret_cast<const float4*>(
                cbase + (size_t)(u0 + u) * NA + 4 * c);
            *reinterpret_cast<float4*>(&scs[u][4 * c]) = v;
        }

        // Phase 1: thread (bl, sub) computes phi for u = u0+sub, +8, ...
        #pragma unroll
        for (int r = 0; r < UCHUNK / 8; r++) {
            int uo = sub + 8 * r;
            int u  = u0 + uo;
            if (u < ucut) {
                float uf  = (float)u;
                float phi = 0.f;
                #pragma unroll
                for (int k = 0; k < NK; k++) {
                    float d = kk[k] - uf;
                    phi += a[k] * __expf(nb[k] * d * d);
                }
                sphi[bl][uo] = phi;
            }
        }
        __syncthreads();

        // Phase 2: pure LDS + FFMA. Thread owns a-cols [sub*10, sub*10+10).
        int uend = min(ucut, u0 + UCHUNK);
        #pragma unroll 2
        for (int u = u0; u < uend; u++) {
            float phi = sphi[bl][u - u0];
            const float* r = &scs[u - u0][sub * APT];
            #pragma unroll
            for (int j = 0; j < APT / 2; j++) {
                float2 c = *reinterpret_cast<const float2*>(r + 2 * j);
                acc[2 * j + 0] = fmaf(phi, c.x, acc[2 * j + 0]);
                acc[2 * j + 1] = fmaf(phi, c.y, acc[2 * j + 1]);
            }
        }
        __syncthreads();
    }

    float2* op = reinterpret_cast<float2*>(out + (size_t)(bt0 + bl) * NA + sub * APT);
    #pragma unroll
    for (int j = 0; j < APT / 2; j++)
        op[j] = make_float2(acc[2 * j], acc[2 * j + 1]);
}

// ---------------------------------------------------------------------------
extern "C" void kernel_launch(void* const* d_in, const int* in_sizes, int n_in,
                              void* d_out, int out_size)
{
    const float* lstm = (const float*)d_in[0];   // [16,1024,512]
    const float* cs   = (const float*)d_in[1];   // [16,600,80]
    const float* W    = (const float*)d_in[2];   // [512,30]
    const float* bias = (const float*)d_in[3];   // [30]
    float* out = (float*)d_out;                  // [16,1024,80]

    (void)in_sizes; (void)n_in; (void)out_size;

    k1_gemm_exp<<<BT / 128, 256>>>(lstm, W, bias);
    k2_window<<<BT / BPB, 256>>>(cs, out);
}